// round 8
// baseline (speedup 1.0000x reference)
#include <cuda_runtime.h>
#include <cstdint>

// LeakageNlinCore as dense M=32768, N=128, K=128 tf32 GEMM via mma.sync.
// Round-8:
//  - B fragments loaded DIRECTLY from global W into registers (64 LDG.32 per
//    thread, 2 W rows per thread, one-compare LOO shift). No G smem, no
//    pre-kernel, no extra sync. W is L2-resident after the first wave.
//  - F in chunked layout (chunk c holds k%4==c): A-fragment loads are
//    LDS.128, conflict-free. Double-buffered, one __syncthreads per tile.

#define NTHREADS 512
#define TILE_M   64
#define TILES    4
#define ROWS_CTA (TILE_M * TILES)   // 256
#define KDIM     128
#define NOUT     128

#define RS 164     // F row stride (floats)
#define CS 40      // F chunk stride (floats)

#define FB_FLOATS  (TILE_M * RS)          // 10496 per buffer
#define SMEM_BYTES (2 * FB_FLOATS * 4)    // 83968 B

__device__ __forceinline__ uint32_t f2tf32(float f) {
    uint32_t r;
    asm("cvt.rna.tf32.f32 %0, %1;" : "=r"(r) : "f"(f));
    return r;
}

__device__ __forceinline__ void mma_16x8x8(float& d0, float& d1, float& d2, float& d3,
                                           uint32_t a0, uint32_t a1, uint32_t a2, uint32_t a3,
                                           uint32_t b0, uint32_t b1) {
    asm volatile(
        "mma.sync.aligned.m16n8k8.row.col.f32.tf32.tf32.f32 "
        "{%0,%1,%2,%3}, {%4,%5,%6,%7}, {%8,%9}, {%0,%1,%2,%3};"
        : "+f"(d0), "+f"(d1), "+f"(d2), "+f"(d3)
        : "r"(a0), "r"(a1), "r"(a2), "r"(a3), "r"(b0), "r"(b1));
}

__global__ void __launch_bounds__(NTHREADS, 1)
leakage_kernel(const float* __restrict__ x, const float* __restrict__ W,
               float* __restrict__ out) {
    extern __shared__ float Fb[];        // [2][64][RS]

    const int tid = threadIdx.x;
    const int wid = tid >> 5;            // 0..15
    const int lid = tid & 31;
    const int g = lid >> 2;
    const int tg = lid & 3;
    const int mg = wid >> 3;             // row half of tile (0/1)
    const int cgrp = wid & 7;            // 16-col group (0..7)
    const size_t t0 = (size_t)blockIdx.x * ROWS_CTA;

    // ---- Issue tile-0 x loads FIRST (DRAM latency hides behind b staging) ----
    float4 r[4];
    {
        const float4* xb = (const float4*)(x + t0 * KDIM);
#pragma unroll
        for (int it = 0; it < 4; it++)
            r[it] = xb[(it * 16 + wid) * 32 + lid];
    }

    // ---- B fragments straight from W: 2 rows/thread, 64 LDG.32 ----
    // b[nb][ks][h] multiplies F[k], k = ks*8 + tg + 4h, for output column
    // n = cgrp*16 + nb*8 + g. W row n holds [fr LOO (63) | fi LOO (63)].
    float b[2][16][2];
#pragma unroll
    for (int nb = 0; nb < 2; nb++) {
        const int n = cgrp * 16 + nb * 8 + g;
        const int c = n >> 1;
        const float* wrow = W + n * 126;
#pragma unroll
        for (int ks = 0; ks < 16; ks++) {
#pragma unroll
            for (int h = 0; h < 2; h++) {
                const int k = ks * 8 + tg + 4 * h;
                const int jj = k & 63;
                const int half = k >> 6;
                float v = 0.0f;
                if (jj != c) {
                    const int p = (jj < c) ? jj : (jj - 1);
                    v = __ldg(wrow + half * 63 + p);
                }
                b[nb][ks][h] = __uint_as_float(f2tf32(v));
            }
        }
    }

#pragma unroll 1
    for (int t = 0; t < TILES; t++) {
        float* buf = Fb + (t & 1) * FB_FLOATS;

        // ---- Transform r -> F (chunked layout), conflict-free STS.32 ----
        const int e0 = (lid & 1) * 2;
        const int p = lid >> 1;
#pragma unroll
        for (int it = 0; it < 4; it++) {
            float4 v = r[it];
            float amp0 = v.x * v.x + v.y * v.y;
            float amp1 = v.z * v.z + v.w * v.w;
            uint32_t fr0 = f2tf32(amp0 * v.x), fi0 = f2tf32(amp0 * v.y);
            uint32_t fr1 = f2tf32(amp1 * v.z), fi1 = f2tf32(amp1 * v.w);
            uint32_t* rowp = (uint32_t*)(buf + (it * 16 + wid) * RS);
            rowp[e0 * CS + p] = fr0;            // k=2l
            rowp[(e0 + 1) * CS + p] = fr1;      // k=2l+1
            rowp[e0 * CS + p + 16] = fi0;       // k=64+2l
            rowp[(e0 + 1) * CS + p + 16] = fi1; // k=65+2l
        }
        __syncthreads();

        // ---- Prefetch next tile's globals ----
        if (t + 1 < TILES) {
            const float4* xb = (const float4*)(x + (t0 + (size_t)(t + 1) * TILE_M) * KDIM);
#pragma unroll
            for (int it = 0; it < 4; it++)
                r[it] = xb[(it * 16 + wid) * 32 + lid];
        }

        // ---- Mainloop: rows [mg*32,+32) x cols [cgrp*16,+16) ----
        float acc[2][2][4];
#pragma unroll
        for (int mt = 0; mt < 2; mt++)
#pragma unroll
            for (int nb = 0; nb < 2; nb++)
#pragma unroll
                for (int q = 0; q < 4; q++) acc[mt][nb][q] = 0.0f;

        const float4* a0p = (const float4*)(buf + (mg * 32 + g) * RS + tg * CS);
        const float4* a1p = (const float4*)(buf + (mg * 32 + g + 8) * RS + tg * CS);
        const float4* a2p = (const float4*)(buf + (mg * 32 + 16 + g) * RS + tg * CS);
        const float4* a3p = (const float4*)(buf + (mg * 32 + 16 + g + 8) * RS + tg * CS);

#pragma unroll
        for (int jj = 0; jj < 8; jj++) {
            float4 q0 = a0p[jj];
            float4 q1 = a1p[jj];
            float4 q2 = a2p[jj];
            float4 q3 = a3p[jj];
#pragma unroll
            for (int s = 0; s < 2; s++) {
                const int ks = 2 * jj + s;
                uint32_t b00 = __float_as_uint(b[0][ks][0]);
                uint32_t b01 = __float_as_uint(b[0][ks][1]);
                uint32_t b10 = __float_as_uint(b[1][ks][0]);
                uint32_t b11 = __float_as_uint(b[1][ks][1]);
                uint32_t a00, a02, a01, a03, a10, a12, a11, a13;
                if (s == 0) {
                    a00 = __float_as_uint(q0.x); a02 = __float_as_uint(q0.y);
                    a01 = __float_as_uint(q1.x); a03 = __float_as_uint(q1.y);
                    a10 = __float_as_uint(q2.x); a12 = __float_as_uint(q2.y);
                    a11 = __float_as_uint(q3.x); a13 = __float_as_uint(q3.y);
                } else {
                    a00 = __float_as_uint(q0.z); a02 = __float_as_uint(q0.w);
                    a01 = __float_as_uint(q1.z); a03 = __float_as_uint(q1.w);
                    a10 = __float_as_uint(q2.z); a12 = __float_as_uint(q2.w);
                    a11 = __float_as_uint(q3.z); a13 = __float_as_uint(q3.w);
                }
                mma_16x8x8(acc[0][0][0], acc[0][0][1], acc[0][0][2], acc[0][0][3],
                           a00, a01, a02, a03, b00, b01);
                mma_16x8x8(acc[0][1][0], acc[0][1][1], acc[0][1][2], acc[0][1][3],
                           a00, a01, a02, a03, b10, b11);
                mma_16x8x8(acc[1][0][0], acc[1][0][1], acc[1][0][2], acc[1][0][3],
                           a10, a11, a12, a13, b00, b01);
                mma_16x8x8(acc[1][1][0], acc[1][1][1], acc[1][1][2], acc[1][1][3],
                           a10, a11, a12, a13, b10, b11);
            }
        }

        // ---- Epilogue: store warp slice ----
        const size_t rbase = t0 + (size_t)t * TILE_M + mg * 32;
#pragma unroll
        for (int mt = 0; mt < 2; mt++) {
#pragma unroll
            for (int nb = 0; nb < 2; nb++) {
                const int col = cgrp * 16 + nb * 8 + tg * 2;
                float* o0 = out + (rbase + mt * 16 + g) * NOUT + col;
                *(float2*)o0 = make_float2(acc[mt][nb][0], acc[mt][nb][1]);
                *(float2*)(o0 + 8 * NOUT) = make_float2(acc[mt][nb][2], acc[mt][nb][3]);
            }
        }
        // No trailing sync: next transform writes the other buffer; the sync
        // at the top of the next iteration (a full barrier) orders reuse.
    }
}

extern "C" void kernel_launch(void* const* d_in, const int* in_sizes, int n_in,
                              void* d_out, int out_size) {
    const float* x = (const float*)d_in[0];  // [B,S,C,2] fp32
    const float* W = (const float*)d_in[1];  // [C,2,126] fp32
    float* out = (float*)d_out;              // [B,S,C,2] fp32

    int tokens = in_sizes[0] / KDIM;         // 32768
    int nblocks = tokens / ROWS_CTA;         // 128

    cudaFuncSetAttribute(leakage_kernel,
                         cudaFuncAttributeMaxDynamicSharedMemorySize, SMEM_BYTES);
    leakage_kernel<<<nblocks, NTHREADS, SMEM_BYTES>>>(x, W, out);
}

// round 9
// speedup vs baseline: 1.0550x; 1.0550x over previous
#include <cuda_runtime.h>
#include <cstdint>

// LeakageNlinCore as dense M=32768, N=128, K=128 tf32 GEMM via mma.sync.
// Round-9 = R6 skeleton + R7 vectorized mainloop + wider g_pack:
//  - Pre-kernel packs G in B-fragment order (dumb coalesced loads in main),
//    launched 64x64 so its scattered-load latency spreads over 64 SMs.
//  - Main: 512 threads, register-resident B (16 LDG.128), chunked-F smem
//    layout (k%4 chunks) giving conflict-free LDS.128 A-fragment loads,
//    double-buffered tiles, one __syncthreads per tile.

#define NTHREADS 512
#define TILE_M   64
#define TILES    4
#define ROWS_CTA (TILE_M * TILES)   // 256
#define KDIM     128
#define NOUT     128

#define RS 164     // F row stride (floats)
#define CS 40      // F chunk stride (floats)

#define FB_FLOATS  (TILE_M * RS)          // 10496 per buffer
#define SMEM_BYTES (2 * FB_FLOATS * 4)    // 83968 B

// Fragment-ordered packed G: [cgrp(8)][j4(16)][lane(32)] float4
__device__ float4 Gpack[8 * 16 * 32];

__device__ __forceinline__ uint32_t f2tf32(float f) {
    uint32_t r;
    asm("cvt.rna.tf32.f32 %0, %1;" : "=r"(r) : "f"(f));
    return r;
}

__device__ __forceinline__ void mma_16x8x8(float& d0, float& d1, float& d2, float& d3,
                                           uint32_t a0, uint32_t a1, uint32_t a2, uint32_t a3,
                                           uint32_t b0, uint32_t b1) {
    asm volatile(
        "mma.sync.aligned.m16n8k8.row.col.f32.tf32.tf32.f32 "
        "{%0,%1,%2,%3}, {%4,%5,%6,%7}, {%8,%9}, {%0,%1,%2,%3};"
        : "+f"(d0), "+f"(d1), "+f"(d2), "+f"(d3)
        : "r"(a0), "r"(a1), "r"(a2), "r"(a3), "r"(b0), "r"(b1));
}

// ---- Pre-kernel: LOO-expand W into B-fragment-ordered Gpack --------------
// Value j (0..63) of slot (cgrp, lane=(g,tg)):
//   nb = j>>5, ks = (j>>1)&15, h = j&1
//   n  = cgrp*16 + nb*8 + g,  k = ks*8 + tg + 4*h
__global__ void g_pack_kernel(const float* __restrict__ W) {
    int idx = blockIdx.x * blockDim.x + threadIdx.x;   // 0..4095
    int cgrp = idx >> 9;
    int j4 = (idx >> 5) & 15;
    int lane = idx & 31;
    int g = lane >> 2, tg = lane & 3;
    float4 v;
    float* pv = (float*)&v;
#pragma unroll
    for (int e = 0; e < 4; e++) {
        int j = j4 * 4 + e;
        int nb = j >> 5, ks = (j >> 1) & 15, h = j & 1;
        int n = cgrp * 16 + nb * 8 + g;
        int k = ks * 8 + tg + 4 * h;
        int c = n >> 1, o = n & 1;
        int jj = k & 63, half = k >> 6;
        float gg = 0.0f;
        if (jj != c) {
            int p = (jj < c) ? jj : (jj - 1);
            gg = W[(c * 2 + o) * 126 + half * 63 + p];
        }
        pv[e] = __uint_as_float(f2tf32(gg));
    }
    Gpack[idx] = v;
}

// ---- Main kernel ----------------------------------------------------------
__global__ void __launch_bounds__(NTHREADS, 1)
leakage_main_kernel(const float* __restrict__ x, float* __restrict__ out) {
    extern __shared__ float Fb[];   // [2][64][RS]

    const int tid = threadIdx.x;
    const int wid = tid >> 5;          // 0..15
    const int lid = tid & 31;
    const int g = lid >> 2;
    const int tg = lid & 3;
    const int mg = wid >> 3;           // row half of tile (0/1)
    const int cgrp = wid & 7;          // 16-col group (0..7)
    const size_t t0 = (size_t)blockIdx.x * ROWS_CTA;

    // ---- Issue tile-0 x loads FIRST (hide DRAM latency behind b staging) ----
    float4 r[4];
    {
        const float4* xb = (const float4*)(x + t0 * KDIM);
#pragma unroll
        for (int it = 0; it < 4; it++)
            r[it] = xb[(it * 16 + wid) * 32 + lid];
    }

    // ---- B slice: 64 regs via 16 coalesced LDG.128 from Gpack ----
    float b[2][16][2];
    {
        const float4* gp = Gpack + cgrp * 512 + lid;
#pragma unroll
        for (int j4 = 0; j4 < 16; j4++) {
            float4 q = gp[j4 * 32];
#pragma unroll
            for (int e = 0; e < 4; e++) {
                const int j = j4 * 4 + e;
                const int nb = j >> 5, ks = (j >> 1) & 15, h = j & 1;
                float val = (e == 0) ? q.x : (e == 1) ? q.y : (e == 2) ? q.z : q.w;
                b[nb][ks][h] = val;
            }
        }
    }

#pragma unroll 1
    for (int t = 0; t < TILES; t++) {
        float* buf = Fb + (t & 1) * FB_FLOATS;

        // ---- Transform r -> F (chunked layout), conflict-free STS.32 ----
        // row = it*16+wid; chunk c holds k%4==c at position k/4, offset c*CS.
        const int e0 = (lid & 1) * 2;
        const int p = lid >> 1;
#pragma unroll
        for (int it = 0; it < 4; it++) {
            float4 v = r[it];
            float amp0 = v.x * v.x + v.y * v.y;
            float amp1 = v.z * v.z + v.w * v.w;
            uint32_t fr0 = f2tf32(amp0 * v.x), fi0 = f2tf32(amp0 * v.y);
            uint32_t fr1 = f2tf32(amp1 * v.z), fi1 = f2tf32(amp1 * v.w);
            uint32_t* rowp = (uint32_t*)(buf + (it * 16 + wid) * RS);
            rowp[e0 * CS + p] = fr0;            // k=2l
            rowp[(e0 + 1) * CS + p] = fr1;      // k=2l+1
            rowp[e0 * CS + p + 16] = fi0;       // k=64+2l
            rowp[(e0 + 1) * CS + p + 16] = fi1; // k=65+2l
        }
        __syncthreads();

        // ---- Prefetch next tile's globals (hidden behind mainloop) ----
        if (t + 1 < TILES) {
            const float4* xb = (const float4*)(x + (t0 + (size_t)(t + 1) * TILE_M) * KDIM);
#pragma unroll
            for (int it = 0; it < 4; it++)
                r[it] = xb[(it * 16 + wid) * 32 + lid];
        }

        // ---- Mainloop: rows [mg*32,+32) x cols [cgrp*16,+16) ----
        float acc[2][2][4];
#pragma unroll
        for (int mt = 0; mt < 2; mt++)
#pragma unroll
            for (int nb = 0; nb < 2; nb++)
#pragma unroll
                for (int q = 0; q < 4; q++) acc[mt][nb][q] = 0.0f;

        // Per-thread A bases: rows {g, g+8, g+16, g+24} of this mg-half, chunk tg.
        const float4* a0p = (const float4*)(buf + (mg * 32 + g) * RS + tg * CS);
        const float4* a1p = (const float4*)(buf + (mg * 32 + g + 8) * RS + tg * CS);
        const float4* a2p = (const float4*)(buf + (mg * 32 + 16 + g) * RS + tg * CS);
        const float4* a3p = (const float4*)(buf + (mg * 32 + 16 + g + 8) * RS + tg * CS);

#pragma unroll
        for (int jj = 0; jj < 8; jj++) {
            // float4 = positions 4jj..4jj+3 = (ks=2jj,h=0),(2jj,1),(2jj+1,0),(2jj+1,1)
            float4 q0 = a0p[jj];
            float4 q1 = a1p[jj];
            float4 q2 = a2p[jj];
            float4 q3 = a3p[jj];
#pragma unroll
            for (int s = 0; s < 2; s++) {
                const int ks = 2 * jj + s;
                uint32_t b00 = __float_as_uint(b[0][ks][0]);
                uint32_t b01 = __float_as_uint(b[0][ks][1]);
                uint32_t b10 = __float_as_uint(b[1][ks][0]);
                uint32_t b11 = __float_as_uint(b[1][ks][1]);
                uint32_t a00, a02, a01, a03, a10, a12, a11, a13;
                if (s == 0) {
                    a00 = __float_as_uint(q0.x); a02 = __float_as_uint(q0.y);
                    a01 = __float_as_uint(q1.x); a03 = __float_as_uint(q1.y);
                    a10 = __float_as_uint(q2.x); a12 = __float_as_uint(q2.y);
                    a11 = __float_as_uint(q3.x); a13 = __float_as_uint(q3.y);
                } else {
                    a00 = __float_as_uint(q0.z); a02 = __float_as_uint(q0.w);
                    a01 = __float_as_uint(q1.z); a03 = __float_as_uint(q1.w);
                    a10 = __float_as_uint(q2.z); a12 = __float_as_uint(q2.w);
                    a11 = __float_as_uint(q3.z); a13 = __float_as_uint(q3.w);
                }
                mma_16x8x8(acc[0][0][0], acc[0][0][1], acc[0][0][2], acc[0][0][3],
                           a00, a01, a02, a03, b00, b01);
                mma_16x8x8(acc[0][1][0], acc[0][1][1], acc[0][1][2], acc[0][1][3],
                           a00, a01, a02, a03, b10, b11);
                mma_16x8x8(acc[1][0][0], acc[1][0][1], acc[1][0][2], acc[1][0][3],
                           a10, a11, a12, a13, b00, b01);
                mma_16x8x8(acc[1][1][0], acc[1][1][1], acc[1][1][2], acc[1][1][3],
                           a10, a11, a12, a13, b10, b11);
            }
        }

        // ---- Epilogue: store warp slice ----
        const size_t rbase = t0 + (size_t)t * TILE_M + mg * 32;
#pragma unroll
        for (int mt = 0; mt < 2; mt++) {
#pragma unroll
            for (int nb = 0; nb < 2; nb++) {
                const int col = cgrp * 16 + nb * 8 + tg * 2;
                float* o0 = out + (rbase + mt * 16 + g) * NOUT + col;
                *(float2*)o0 = make_float2(acc[mt][nb][0], acc[mt][nb][1]);
                *(float2*)(o0 + 8 * NOUT) = make_float2(acc[mt][nb][2], acc[mt][nb][3]);
            }
        }
        // No trailing sync: next transform writes the other buffer; the sync
        // at the top of the next iteration orders reuse of this one.
    }
}

extern "C" void kernel_launch(void* const* d_in, const int* in_sizes, int n_in,
                              void* d_out, int out_size) {
    const float* x = (const float*)d_in[0];  // [B,S,C,2] fp32
    const float* W = (const float*)d_in[1];  // [C,2,126] fp32
    float* out = (float*)d_out;              // [B,S,C,2] fp32

    int tokens = in_sizes[0] / KDIM;         // 32768
    int nblocks = tokens / ROWS_CTA;         // 128

    g_pack_kernel<<<64, 64>>>(W);            // 64 SMs -> latency spread
    cudaFuncSetAttribute(leakage_main_kernel,
                         cudaFuncAttributeMaxDynamicSharedMemorySize, SMEM_BYTES);
    leakage_main_kernel<<<nblocks, NTHREADS, SMEM_BYTES>>>(x, out);
}

// round 10
// speedup vs baseline: 1.0838x; 1.0273x over previous
#include <cuda_runtime.h>
#include <cstdint>

// LeakageNlinCore as dense M=32768, N=128, K=128 tf32 GEMM via mma.sync.
// Round-10: 256-thread CTAs with 2 CTAs/SM (barrier/phase bubbles of one CTA
// filled by the other), R6's measured-best scalar-LDS mainloop, R9's 64x64
// g_pack pre-kernel. Warp slice = 32 rows x 16 cols; B register-resident.

#define NTHREADS 256
#define TILE_M   32
#define TILES    4
#define ROWS_CTA (TILE_M * TILES)   // 128
#define KDIM     128
#define NOUT     128
#define STRIDE   132                // padded F row stride (floats)

#define FB_FLOATS (TILE_M * STRIDE)          // 4224 per buffer
#define SMEM_BYTES (2 * FB_FLOATS * 4)       // 33792 B -> 2 CTAs/SM

// Fragment-ordered packed G: [cgrp(8)][j4(16)][lane(32)] float4
__device__ float4 Gpack[8 * 16 * 32];

__device__ __forceinline__ uint32_t f2tf32(float f) {
    uint32_t r;
    asm("cvt.rna.tf32.f32 %0, %1;" : "=r"(r) : "f"(f));
    return r;
}

__device__ __forceinline__ void mma_16x8x8(float& d0, float& d1, float& d2, float& d3,
                                           uint32_t a0, uint32_t a1, uint32_t a2, uint32_t a3,
                                           uint32_t b0, uint32_t b1) {
    asm volatile(
        "mma.sync.aligned.m16n8k8.row.col.f32.tf32.tf32.f32 "
        "{%0,%1,%2,%3}, {%4,%5,%6,%7}, {%8,%9}, {%0,%1,%2,%3};"
        : "+f"(d0), "+f"(d1), "+f"(d2), "+f"(d3)
        : "r"(a0), "r"(a1), "r"(a2), "r"(a3), "r"(b0), "r"(b1));
}

// ---- Pre-kernel: LOO-expand W into B-fragment-ordered Gpack --------------
// Value j (0..63) of slot (cgrp, lane=(g,tg)):
//   nb = j>>5, ks = (j>>1)&15, h = j&1
//   n  = cgrp*16 + nb*8 + g,  k = ks*8 + tg + 4*h
__global__ void g_pack_kernel(const float* __restrict__ W) {
    int idx = blockIdx.x * blockDim.x + threadIdx.x;   // 0..4095
    int cgrp = idx >> 9;
    int j4 = (idx >> 5) & 15;
    int lane = idx & 31;
    int g = lane >> 2, tg = lane & 3;
    float4 v;
    float* pv = (float*)&v;
#pragma unroll
    for (int e = 0; e < 4; e++) {
        int j = j4 * 4 + e;
        int nb = j >> 5, ks = (j >> 1) & 15, h = j & 1;
        int n = cgrp * 16 + nb * 8 + g;
        int k = ks * 8 + tg + 4 * h;
        int c = n >> 1, o = n & 1;
        int jj = k & 63, half = k >> 6;
        float gg = 0.0f;
        if (jj != c) {
            int p = (jj < c) ? jj : (jj - 1);
            gg = W[(c * 2 + o) * 126 + half * 63 + p];
        }
        pv[e] = __uint_as_float(f2tf32(gg));
    }
    Gpack[idx] = v;
}

// ---- Main kernel ----------------------------------------------------------
__global__ void __launch_bounds__(NTHREADS, 2)
leakage_main_kernel(const float* __restrict__ x, float* __restrict__ out) {
    __shared__ float Fb[2 * FB_FLOATS];   // [2][32][132]

    const int tid = threadIdx.x;
    const int wid = tid >> 5;            // 0..7
    const int lid = tid & 31;
    const int g = lid >> 2;
    const int tg = lid & 3;
    const int cgrp = wid;                // 16-col group (0..7)
    const size_t t0 = (size_t)blockIdx.x * ROWS_CTA;

    // ---- Issue tile-0 x loads FIRST (hide DRAM latency behind b staging) ----
    float4 r[4];
    {
        const float4* xb = (const float4*)(x + t0 * KDIM);
#pragma unroll
        for (int it = 0; it < 4; it++)
            r[it] = xb[(it * 8 + wid) * 32 + lid];
    }

    // ---- B slice: 64 regs via 16 coalesced LDG.128 from Gpack ----
    float b[2][16][2];
    {
        const float4* gp = Gpack + cgrp * 512 + lid;
#pragma unroll
        for (int j4 = 0; j4 < 16; j4++) {
            float4 q = gp[j4 * 32];
#pragma unroll
            for (int e = 0; e < 4; e++) {
                const int j = j4 * 4 + e;
                const int nb = j >> 5, ks = (j >> 1) & 15, h = j & 1;
                float val = (e == 0) ? q.x : (e == 1) ? q.y : (e == 2) ? q.z : q.w;
                b[nb][ks][h] = val;
            }
        }
    }

#pragma unroll 1
    for (int t = 0; t < TILES; t++) {
        float* buf = Fb + (t & 1) * FB_FLOATS;

        // ---- Transform r -> F (row = it*8+wid, channel pair = lid) ----
#pragma unroll
        for (int it = 0; it < 4; it++) {
            float4 v = r[it];
            float amp0 = v.x * v.x + v.y * v.y;
            float amp1 = v.z * v.z + v.w * v.w;
            uint32_t fr0 = f2tf32(amp0 * v.x), fi0 = f2tf32(amp0 * v.y);
            uint32_t fr1 = f2tf32(amp1 * v.z), fi1 = f2tf32(amp1 * v.w);
            uint32_t* rowp = (uint32_t*)(buf + (it * 8 + wid) * STRIDE);
            int c0 = lid * 2;
            *(uint2*)(rowp + c0) = make_uint2(fr0, fr1);        // fr -> [0,64)
            *(uint2*)(rowp + 64 + c0) = make_uint2(fi0, fi1);   // fi -> [64,128)
        }
        __syncthreads();

        // ---- Prefetch next tile's globals (hidden behind mainloop) ----
        if (t + 1 < TILES) {
            const float4* xb = (const float4*)(x + (t0 + (size_t)(t + 1) * TILE_M) * KDIM);
#pragma unroll
            for (int it = 0; it < 4; it++)
                r[it] = xb[(it * 8 + wid) * 32 + lid];
        }

        // ---- Mainloop: all 32 tile rows x cols [cgrp*16,+16) ----
        float acc[2][2][4];
#pragma unroll
        for (int mt = 0; mt < 2; mt++)
#pragma unroll
            for (int nb = 0; nb < 2; nb++)
#pragma unroll
                for (int q = 0; q < 4; q++) acc[mt][nb][q] = 0.0f;

        const uint32_t* F = (const uint32_t*)buf;
#pragma unroll
        for (int ks = 0; ks < 16; ks++) {
            const int k0 = ks * 8 + tg;
            uint32_t a[2][4];
#pragma unroll
            for (int mt = 0; mt < 2; mt++) {
                const uint32_t* f0 = F + (mt * 16 + g) * STRIDE + k0;
                const uint32_t* f1 = F + (mt * 16 + g + 8) * STRIDE + k0;
                a[mt][0] = f0[0];
                a[mt][1] = f1[0];
                a[mt][2] = f0[4];
                a[mt][3] = f1[4];
            }
            uint32_t b00 = __float_as_uint(b[0][ks][0]);
            uint32_t b01 = __float_as_uint(b[0][ks][1]);
            uint32_t b10 = __float_as_uint(b[1][ks][0]);
            uint32_t b11 = __float_as_uint(b[1][ks][1]);
#pragma unroll
            for (int mt = 0; mt < 2; mt++) {
                mma_16x8x8(acc[mt][0][0], acc[mt][0][1], acc[mt][0][2], acc[mt][0][3],
                           a[mt][0], a[mt][1], a[mt][2], a[mt][3], b00, b01);
                mma_16x8x8(acc[mt][1][0], acc[mt][1][1], acc[mt][1][2], acc[mt][1][3],
                           a[mt][0], a[mt][1], a[mt][2], a[mt][3], b10, b11);
            }
        }

        // ---- Epilogue: store warp slice ----
        const size_t rbase = t0 + (size_t)t * TILE_M;
#pragma unroll
        for (int mt = 0; mt < 2; mt++) {
#pragma unroll
            for (int nb = 0; nb < 2; nb++) {
                const int col = cgrp * 16 + nb * 8 + tg * 2;
                float* o0 = out + (rbase + mt * 16 + g) * NOUT + col;
                *(float2*)o0 = make_float2(acc[mt][nb][0], acc[mt][nb][1]);
                *(float2*)(o0 + 8 * NOUT) = make_float2(acc[mt][nb][2], acc[mt][nb][3]);
            }
        }
        // Next transform writes the other buffer; the sync at the top of the
        // next iteration orders reuse of this one.
        __syncthreads();
    }
}

extern "C" void kernel_launch(void* const* d_in, const int* in_sizes, int n_in,
                              void* d_out, int out_size) {
    const float* x = (const float*)d_in[0];  // [B,S,C,2] fp32
    const float* W = (const float*)d_in[1];  // [C,2,126] fp32
    float* out = (float*)d_out;              // [B,S,C,2] fp32

    int tokens = in_sizes[0] / KDIM;         // 32768
    int nblocks = tokens / ROWS_CTA;         // 256

    g_pack_kernel<<<64, 64>>>(W);
    leakage_main_kernel<<<nblocks, NTHREADS>>>(x, out);
}